// round 15
// baseline (speedup 1.0000x reference)
#include <cuda_runtime.h>
#include <cuda_bf16.h>
#include <cstdint>

#define EMB   1024
#define NHEAD 16
#define HDIM  64
#define BATCH 4
#define SEQ   2048
#define MTOT  (BATCH*SEQ)

// GEMM tensor-core config
#define GKC        64
#define TILE_B     16384
#define STAGE_B    (4*TILE_B)
#define GSMEM      (1024 + 2*STAGE_B) // 132096 bytes

// Attention config
#define AQ 128
#define AK 128
#define NT (SEQ/AK)
// attention smem offsets (bytes). K double-buffered, V single, P single.
#define A_HMAX    64
#define A_HSUM    1088
#define A_QH      3072
#define A_QL      (A_QH  + 16384)
#define A_K0      (A_QL  + 16384)
#define A_K1      (A_K0  + 32768)
#define A_VTH     (A_K1  + 32768)
#define A_VTL     (A_VTH + 16384)
#define A_PH      (A_VTL + 16384)
#define A_PL      (A_PH  + 32768)
#define ASMEM     (A_PL  + 32768)    // 199680

// GEMM output modes
#define GM_F32    0   // fp32 C
#define GM_SPLIT  1   // bf16 hi/lo planes [row][col], scaled
#define GM_SPLITT 2   // bf16 hi/lo planes transposed [b*1024+col][s]

// Scratch (device-global: allocation-guard-safe)
__device__ __nv_bfloat16 g_qh[MTOT*EMB];
__device__ __nv_bfloat16 g_ql[MTOT*EMB];
__device__ __nv_bfloat16 g_kh[MTOT*EMB];
__device__ __nv_bfloat16 g_kl[MTOT*EMB];
__device__ __nv_bfloat16 g_vth[MTOT*EMB];
__device__ __nv_bfloat16 g_vtl[MTOT*EMB];
__device__ float g_ctx[MTOT*EMB];

__device__ __forceinline__ float ex2f(float x) {
    float y; asm("ex2.approx.ftz.f32 %0, %1;" : "=f"(y) : "f"(x)); return y;
}

#if defined(__CUDA_ARCH_FEAT_SM103_ALL) || !defined(__CUDA_ARCH__)
#define HAS_TCGEN05 1
#else
#define HAS_TCGEN05 0
#endif

#if HAS_TCGEN05
// ---------------- tcgen05 helpers (parsed on host; emitted only on sm_103a) ----
__device__ __forceinline__ uint32_t elect_one() {
    uint32_t pr;
    asm volatile("{\n\t.reg .pred p;\n\telect.sync _|p, 0xFFFFFFFF;\n\t"
                 "selp.b32 %0, 1, 0, p;\n\t}" : "=r"(pr));
    return pr;
}
__device__ __forceinline__ uint64_t mkdesc(uint32_t addr) {  // SW128 K-major, LBO=1, SBO=64
    const uint64_t base = (uint64_t(2) << 61) | (uint64_t(1) << 46)
                        | (uint64_t(64) << 32) | (uint64_t(1) << 16);
    return base | ((uint64_t)(addr >> 4) & 0x3FFF);
}
__device__ __forceinline__ void mma_f16_ss(uint32_t d, uint64_t ad, uint64_t bd,
                                           uint32_t idesc, uint32_t en) {
    asm volatile("{\n\t.reg .pred p;\n\tsetp.ne.u32 p, %5, 0;\n\t"
        "tcgen05.mma.cta_group::1.kind::f16 [%0], %1, %2, %3, {%4,%4,%4,%4}, p;\n\t}"
        :: "r"(d), "l"(ad), "l"(bd), "r"(idesc), "r"(0u), "r"(en) : "memory");
}
#define TC_COMMIT(a) \
    asm volatile("tcgen05.commit.cta_group::1.mbarrier::arrive::one.shared::cluster.b64 [%0];" \
                 :: "r"(a) : "memory")
#define TC_ALLOC(sres, n) \
    asm volatile("tcgen05.alloc.cta_group::1.sync.aligned.shared::cta.b32 [%0], %1;" \
                 :: "r"(sres), "r"((uint32_t)(n)) : "memory")
#define TC_DEALLOC(tm, n) \
    asm volatile("tcgen05.dealloc.cta_group::1.sync.aligned.b32 %0, %1;" :: "r"(tm), "r"((uint32_t)(n)))
#define TC_RELINQ() asm volatile("tcgen05.relinquish_alloc_permit.cta_group::1.sync.aligned;")
#define TC_FENCE_AFTER()  asm volatile("tcgen05.fence::after_thread_sync;" ::: "memory")
#define TC_FENCE_BEFORE() asm volatile("tcgen05.fence::before_thread_sync;" ::: "memory")
#define TC_WAIT_LD() asm volatile("tcgen05.wait::ld.sync.aligned;" ::: "memory")
#define LDTM_X32(r, a) \
    asm volatile("tcgen05.ld.sync.aligned.32x32b.x32.b32 "                        \
        "{%0,%1,%2,%3,%4,%5,%6,%7,%8,%9,%10,%11,%12,%13,%14,%15,"                 \
        "%16,%17,%18,%19,%20,%21,%22,%23,%24,%25,%26,%27,%28,%29,%30,%31}, [%32];"\
        : "=r"((r)[0]),"=r"((r)[1]),"=r"((r)[2]),"=r"((r)[3]),                    \
          "=r"((r)[4]),"=r"((r)[5]),"=r"((r)[6]),"=r"((r)[7]),                    \
          "=r"((r)[8]),"=r"((r)[9]),"=r"((r)[10]),"=r"((r)[11]),                  \
          "=r"((r)[12]),"=r"((r)[13]),"=r"((r)[14]),"=r"((r)[15]),                \
          "=r"((r)[16]),"=r"((r)[17]),"=r"((r)[18]),"=r"((r)[19]),                \
          "=r"((r)[20]),"=r"((r)[21]),"=r"((r)[22]),"=r"((r)[23]),                \
          "=r"((r)[24]),"=r"((r)[25]),"=r"((r)[26]),"=r"((r)[27]),                \
          "=r"((r)[28]),"=r"((r)[29]),"=r"((r)[30]),"=r"((r)[31])                 \
        : "r"(a))
#endif // HAS_TCGEN05 helpers

// ---- arch-independent helpers ----
__device__ __forceinline__ uint32_t smem_u32(const void* p) {
    uint32_t a;
    asm("{ .reg .u64 t; cvta.to.shared.u64 t, %1; cvt.u32.u64 %0, t; }"
        : "=r"(a) : "l"(p));
    return a;
}
#define MBAR_INIT(a, n) \
    asm volatile("mbarrier.init.shared.b64 [%0], %1;" :: "r"(a), "r"(n) : "memory")
#define MBAR_WAIT(a, par) do {                                                    \
    uint32_t _m = (a), _p = (par), _d;                                            \
    asm volatile("{\n\t.reg .pred p;\n\t"                                         \
        "mbarrier.try_wait.parity.acquire.cta.shared::cta.b64 p, [%1], %2;\n\t"   \
        "selp.b32 %0, 1, 0, p;\n\t}" : "=r"(_d) : "r"(_m), "r"(_p) : "memory");   \
    if (!_d) {                                                                    \
        asm volatile("{\n\t.reg .pred P1;\n\tWL_%=:\n\t"                          \
            "mbarrier.try_wait.parity.acquire.cta.shared::cta.b64 P1, [%0], %1, 0x989680;\n\t" \
            "@P1 bra.uni WD_%=;\n\tbra.uni WL_%=;\n\tWD_%=:\n\t}"                 \
            :: "r"(_m), "r"(_p) : "memory");                                      \
    } } while (0)
#define FENCE_PROXY() asm volatile("fence.proxy.async.shared::cta;" ::: "memory")

__device__ __forceinline__ uint32_t pk2(__nv_bfloat16 lo, __nv_bfloat16 hi) {
    return (uint32_t)__bfloat16_as_ushort(lo) | ((uint32_t)__bfloat16_as_ushort(hi) << 16);
}

// idescs: F32 acc, BF16 a/b, M=128 (both K-major — validated forms)
#define GIDESC   ((1u<<4)|(1u<<7)|(1u<<10)|((128u/8)<<17)|((128u/16)<<24))  // N=128
#define IDESC_PV ((1u<<4)|(1u<<7)|(1u<<10)|(( 64u/8)<<17)|((128u/16)<<24))  // N=64

// ---------------------------------------------------------------------------
// C = A[M,K] * W[N,K]^T, output mode selects fp32 / split-bf16 / split-transposed.
// ---------------------------------------------------------------------------
__global__ void __launch_bounds__(256, 1)
gemm_tc_kernel(const float* __restrict__ A, const float* __restrict__ W,
               float* __restrict__ C,
               __nv_bfloat16* __restrict__ Ch, __nv_bfloat16* __restrict__ Cl,
               int mode, float oscale) {
    extern __shared__ __align__(1024) char smem[];
    const int t = threadIdx.x;
    const int bm = blockIdx.y << 7, bn = blockIdx.x << 7;

#if HAS_TCGEN05
    const uint32_t sb = smem_u32(smem);
    const int wid = t >> 5, lane = t & 31;
    const uint32_t TMP   = sb;
    const uint32_t MB0   = sb + 16;
    const uint32_t MB1   = sb + 24;
    const uint32_t TILES = sb + 1024;

    if (t == 0) { MBAR_INIT(MB0, 1); MBAR_INIT(MB1, 1); }
    if (wid == 0) TC_ALLOC(TMP, 128);
    __syncthreads();
    uint32_t tmem;
    asm volatile("ld.shared.b32 %0, [%1];" : "=r"(tmem) : "r"(TMP));

    int ph0 = 0, ph1 = 0;

    for (int c = 0; c < EMB / GKC; c++) {
        const int buf = c & 1;
        if (c >= 2) {
            if (buf == 0) { MBAR_WAIT(MB0, ph0 & 1); ph0++; }
            else          { MBAR_WAIT(MB1, ph1 & 1); ph1++; }
        }
        const uint32_t stage = TILES + buf * STAGE_B;
#pragma unroll
        for (int it = 0; it < 8; it++) {
            int idx = it * 256 + t;
            int row = idx >> 4, g4 = idx & 15;
            float4 av = *(const float4*)(A + (size_t)(bm + row) * EMB + c * GKC + g4 * 4);
            float4 wv = *(const float4*)(W + (size_t)(bn + row) * EMB + c * GKC + g4 * 4);
            uint32_t off = row * 128 + g4 * 8;
            uint32_t sw  = off ^ ((off >> 3) & 0x70);
            float af[4] = {av.x, av.y, av.z, av.w};
            float wf[4] = {wv.x, wv.y, wv.z, wv.w};
            __nv_bfloat16 ah[4], al[4], wh[4], wl[4];
#pragma unroll
            for (int u = 0; u < 4; u++) {
                ah[u] = __float2bfloat16(af[u]);
                al[u] = __float2bfloat16(af[u] - __bfloat162float(ah[u]));
                wh[u] = __float2bfloat16(wf[u]);
                wl[u] = __float2bfloat16(wf[u] - __bfloat162float(wh[u]));
            }
            char* stp = smem + (stage - sb);
            *(uint2*)(stp + 0 * TILE_B + sw) = make_uint2(pk2(ah[0], ah[1]), pk2(ah[2], ah[3]));
            *(uint2*)(stp + 1 * TILE_B + sw) = make_uint2(pk2(al[0], al[1]), pk2(al[2], al[3]));
            *(uint2*)(stp + 2 * TILE_B + sw) = make_uint2(pk2(wh[0], wh[1]), pk2(wh[2], wh[3]));
            *(uint2*)(stp + 3 * TILE_B + sw) = make_uint2(pk2(wl[0], wl[1]), pk2(wl[2], wl[3]));
        }
        FENCE_PROXY();
        __syncthreads();

        if (wid == 0 && elect_one()) {
            uint64_t dAh = mkdesc(stage + 0 * TILE_B);
            uint64_t dAl = mkdesc(stage + 1 * TILE_B);
            uint64_t dBh = mkdesc(stage + 2 * TILE_B);
            uint64_t dBl = mkdesc(stage + 3 * TILE_B);
#pragma unroll
            for (int ks = 0; ks < 4; ks++) {
                uint32_t en0 = !(c == 0 && ks == 0);
                mma_f16_ss(tmem, dAh + ks * 2, dBh + ks * 2, GIDESC, en0);
                mma_f16_ss(tmem, dAh + ks * 2, dBl + ks * 2, GIDESC, 1u);
                mma_f16_ss(tmem, dAl + ks * 2, dBh + ks * 2, GIDESC, 1u);
            }
            TC_COMMIT(buf ? MB1 : MB0);
        }
    }

    MBAR_WAIT(MB0, ph0 & 1);
    MBAR_WAIT(MB1, ph1 & 1);
    TC_FENCE_AFTER();

    {
        const int half = wid >> 2, sub = wid & 3;
        const int row = bm + sub * 32 + lane;
#pragma unroll
        for (int cb = 0; cb < 2; cb++) {
            uint32_t col = (uint32_t)(half * 64 + cb * 32);
            uint32_t r[32];
            LDTM_X32(r, tmem + col);
            TC_WAIT_LD();
            if (mode == GM_F32) {
                float* Cp = C + (size_t)row * EMB + bn + col;
#pragma unroll
                for (int j = 0; j < 8; j++) {
                    *(float4*)(Cp + j * 4) = make_float4(
                        __uint_as_float(r[4 * j + 0]), __uint_as_float(r[4 * j + 1]),
                        __uint_as_float(r[4 * j + 2]), __uint_as_float(r[4 * j + 3]));
                }
            } else if (mode == GM_SPLIT) {
                __nv_bfloat16* Hp = Ch + (size_t)row * EMB + bn + col;
                __nv_bfloat16* Lp = Cl + (size_t)row * EMB + bn + col;
#pragma unroll
                for (int j4 = 0; j4 < 8; j4++) {
                    __nv_bfloat16 hh[4], ll[4];
#pragma unroll
                    for (int u = 0; u < 4; u++) {
                        float f = __uint_as_float(r[4 * j4 + u]) * oscale;
                        hh[u] = __float2bfloat16(f);
                        ll[u] = __float2bfloat16(f - __bfloat162float(hh[u]));
                    }
                    *(uint2*)(Hp + j4 * 4) = make_uint2(pk2(hh[0], hh[1]), pk2(hh[2], hh[3]));
                    *(uint2*)(Lp + j4 * 4) = make_uint2(pk2(ll[0], ll[1]), pk2(ll[2], ll[3]));
                }
            } else {  // GM_SPLITT: transposed planes [bb*1024 + colg][s]
                const int bb = row >> 11, s = row & 2047;
#pragma unroll
                for (int j = 0; j < 32; j++) {
                    int colg = bn + (int)col + j;
                    float f = __uint_as_float(r[j]);
                    __nv_bfloat16 hv = __float2bfloat16(f);
                    __nv_bfloat16 lv = __float2bfloat16(f - __bfloat162float(hv));
                    size_t dst = ((size_t)bb * 1024 + colg) * SEQ + s;
                    Ch[dst] = hv;
                    Cl[dst] = lv;
                }
            }
        }
        TC_FENCE_BEFORE();
    }
    __syncthreads();
    if (wid == 0) { TC_RELINQ(); TC_DEALLOC(tmem, 128); }

#else  // ---------------- SIMT fallback (non-sm_103a device binaries) ---------
    float* As = (float*)smem;
    float* Bs = (float*)smem + 8 * 128;
    const int tx = t & 15, ty = t >> 4;
    const int lrow = t >> 1, lk = (t & 1) << 2;
    const float* Ap = A + (size_t)(bm + lrow) * EMB + lk;
    const float* Wp = W + (size_t)(bn + lrow) * EMB + lk;

    float acc[8][8];
#pragma unroll
    for (int i = 0; i < 8; i++)
#pragma unroll
        for (int j = 0; j < 8; j++) acc[i][j] = 0.f;

    for (int k0 = 0; k0 < EMB; k0 += 8) {
        float4 av = *(const float4*)(Ap + k0);
        float4 wv = *(const float4*)(Wp + k0);
        __syncthreads();
        As[(lk+0)*128+lrow] = av.x; As[(lk+1)*128+lrow] = av.y;
        As[(lk+2)*128+lrow] = av.z; As[(lk+3)*128+lrow] = av.w;
        Bs[(lk+0)*128+lrow] = wv.x; Bs[(lk+1)*128+lrow] = wv.y;
        Bs[(lk+2)*128+lrow] = wv.z; Bs[(lk+3)*128+lrow] = wv.w;
        __syncthreads();
#pragma unroll
        for (int kk = 0; kk < 8; kk++) {
            float4 a0 = *(const float4*)&As[kk*128 + (ty << 2)];
            float4 a1 = *(const float4*)&As[kk*128 + 64 + (ty << 2)];
            float4 b0 = *(const float4*)&Bs[kk*128 + (tx << 2)];
            float4 b1 = *(const float4*)&Bs[kk*128 + 64 + (tx << 2)];
            float ar[8] = {a0.x,a0.y,a0.z,a0.w, a1.x,a1.y,a1.z,a1.w};
            float br[8] = {b0.x,b0.y,b0.z,b0.w, b1.x,b1.y,b1.z,b1.w};
#pragma unroll
            for (int i = 0; i < 8; i++)
#pragma unroll
                for (int j = 0; j < 8; j++)
                    acc[i][j] += ar[i] * br[j];
        }
    }
#pragma unroll
    for (int i = 0; i < 8; i++) {
        int r = bm + ((i < 4) ? ((ty << 2) + i) : (64 + (ty << 2) + i - 4));
#pragma unroll
        for (int jj = 0; jj < 8; jj++) {
            int colg = bn + ((jj < 4) ? (tx << 2) + jj : 64 + (tx << 2) + jj - 4);
            float f = acc[i][jj];
            if (mode == GM_F32) {
                C[(size_t)r * EMB + colg] = f;
            } else if (mode == GM_SPLIT) {
                f *= oscale;
                __nv_bfloat16 hv = __float2bfloat16(f);
                Ch[(size_t)r * EMB + colg] = hv;
                Cl[(size_t)r * EMB + colg] = __float2bfloat16(f - __bfloat162float(hv));
            } else {
                __nv_bfloat16 hv = __float2bfloat16(f);
                size_t dst = ((size_t)(r >> 11) * 1024 + colg) * SEQ + (r & 2047);
                Ch[dst] = hv;
                Cl[dst] = __float2bfloat16(f - __bfloat162float(hv));
            }
        }
    }
#endif
}

// ---------------------------------------------------------------------------
// Tensor-core flash attention. Q/K/V are pre-split bf16 planes produced by the
// GEMMs (Q pre-scaled); K/V smem fills are pure LDG.64->STS.64 copies, V from
// pre-transposed planes (conflict-free stores, validated R12 layout).
// ---------------------------------------------------------------------------
__global__ void __launch_bounds__(256, 1)
attention_kernel(const __nv_bfloat16* __restrict__ Qh, const __nv_bfloat16* __restrict__ Ql,
                 const __nv_bfloat16* __restrict__ Kh, const __nv_bfloat16* __restrict__ Kl,
                 const __nv_bfloat16* __restrict__ Vth, const __nv_bfloat16* __restrict__ Vtl,
                 float* __restrict__ O) {
    extern __shared__ __align__(1024) char smem[];
    const int t = threadIdx.x;
    const int qt = blockIdx.x, h = blockIdx.y, b = blockIdx.z;
    const size_t rowbase = (size_t)b * SEQ;

#if HAS_TCGEN05
    const uint32_t sb = smem_u32(smem);
    const int wid = t >> 5, lane = t & 31;
    const int sub = wid & 3, half = wid >> 2;
    const int row = sub * 32 + lane;

    const uint32_t TMP = sb;
    const uint32_t MBS = sb + 16;
    const uint32_t MBP = sb + 24;
    float* halfmax = (float*)(smem + A_HMAX);
    float* halfsum = (float*)(smem + A_HSUM);

    if (t == 0) { MBAR_INIT(MBS, 1); MBAR_INIT(MBP, 1); }
    if (wid == 0) TC_ALLOC(TMP, 256);
    __syncthreads();
    uint32_t tmem;
    asm volatile("ld.shared.b32 %0, [%1];" : "=r"(tmem) : "r"(TMP));
    const uint32_t tm_s = tmem;
    const uint32_t tm_o = tmem + 128;

    const __nv_bfloat16* Qhp = Qh + (rowbase + (size_t)qt * AQ) * EMB + h * HDIM;
    const __nv_bfloat16* Qlp = Ql + (rowbase + (size_t)qt * AQ) * EMB + h * HDIM;
    const __nv_bfloat16* Khp = Kh + rowbase * EMB + h * HDIM;
    const __nv_bfloat16* Klp = Kl + rowbase * EMB + h * HDIM;
    const __nv_bfloat16* Vthp = Vth + ((size_t)b * 1024 + h * HDIM) * SEQ;
    const __nv_bfloat16* Vtlp = Vtl + ((size_t)b * 1024 + h * HDIM) * SEQ;

    // ---- Load Q (pre-scaled, pre-split): pure copies ----
#pragma unroll
    for (int it = 0; it < 8; it++) {
        int idx = it * 256 + t;
        int r = idx >> 4, g4 = idx & 15;
        uint2 qhv = *(const uint2*)(Qhp + (size_t)r * EMB + g4 * 4);
        uint2 qlv = *(const uint2*)(Qlp + (size_t)r * EMB + g4 * 4);
        uint32_t off = r * 128 + g4 * 8;
        uint32_t sw  = off ^ ((off >> 3) & 0x70);
        *(uint2*)(smem + A_QH + sw) = qhv;
        *(uint2*)(smem + A_QL + sw) = qlv;
    }

    // ---- Prologue: load K(0) into stage 0, issue S(0) ----
#pragma unroll
    for (int it = 0; it < 8; it++) {
        int idx = it * 256 + t;
        int key = idx >> 4, g4 = idx & 15;
        uint2 khv = *(const uint2*)(Khp + (size_t)key * EMB + g4 * 4);
        uint2 klv = *(const uint2*)(Klp + (size_t)key * EMB + g4 * 4);
        uint32_t off = key * 128 + g4 * 8;
        uint32_t sw  = off ^ ((off >> 3) & 0x70);
        *(uint2*)(smem + A_K0 + sw)         = khv;
        *(uint2*)(smem + A_K0 + 16384 + sw) = klv;
    }
    FENCE_PROXY();
    __syncthreads();

    const uint64_t dQh = mkdesc(sb + A_QH);
    const uint64_t dQl = mkdesc(sb + A_QL);
    const uint64_t dKh[2] = { mkdesc(sb + A_K0),         mkdesc(sb + A_K1) };
    const uint64_t dKl[2] = { mkdesc(sb + A_K0 + 16384), mkdesc(sb + A_K1 + 16384) };
    const uint64_t dVh = mkdesc(sb + A_VTH);
    const uint64_t dVl = mkdesc(sb + A_VTL);
    const uint64_t dPh = mkdesc(sb + A_PH);
    const uint64_t dPl = mkdesc(sb + A_PL);

    if (wid == 0 && elect_one()) {
        TC_FENCE_AFTER();
#pragma unroll
        for (int ks = 0; ks < 4; ks++) {
            mma_f16_ss(tm_s, dQh + ks * 2, dKh[0] + ks * 2, GIDESC, ks != 0);
            mma_f16_ss(tm_s, dQh + ks * 2, dKl[0] + ks * 2, GIDESC, 1u);
            mma_f16_ss(tm_s, dQl + ks * 2, dKh[0] + ks * 2, GIDESC, 1u);
        }
        TC_COMMIT(MBS);
    }

    float m = -__int_as_float(0x7f800000);
    float l = 0.f;
    float o_acc[32];
#pragma unroll
    for (int j = 0; j < 32; j++) o_acc[j] = 0.f;

    // V-store assignment (validated R12): thread owns (d = t>>2, keys [kg*32,+32))
    const int vd = t >> 2, vkg = t & 3;
    const uint32_t vbase = (uint32_t)((vkg >> 1) * 8192 + (vd >> 3) * 1024
                                    + (vd & 7) * 128 + (vkg & 1) * 64);
    const __nv_bfloat16* VthD = Vthp + (size_t)vd * SEQ;
    const __nv_bfloat16* VtlD = Vtlp + (size_t)vd * SEQ;

    for (int kt = 0; kt < NT; kt++) {
        // ---- overlap with in-flight S(kt): copy V(kt) and K(kt+1) ----
#pragma unroll
        for (int j = 0; j < 8; j++) {
            int koff = kt * AK + vkg * 32 + 4 * j;
            uint2 hv = *(const uint2*)(VthD + koff);
            uint2 lv = *(const uint2*)(VtlD + koff);
            uint32_t off = vbase + j * 8;
            uint32_t sw  = off ^ ((off >> 3) & 0x70);
            *(uint2*)(smem + A_VTH + sw) = hv;
            *(uint2*)(smem + A_VTL + sw) = lv;
        }
        if (kt + 1 < NT) {
            const uint32_t kst = ((kt + 1) & 1) ? A_K1 : A_K0;
#pragma unroll
            for (int it = 0; it < 8; it++) {
                int idx = it * 256 + t;
                int key = idx >> 4, g4 = idx & 15;
                uint2 khv = *(const uint2*)(Khp + (size_t)((kt + 1) * AK + key) * EMB + g4 * 4);
                uint2 klv = *(const uint2*)(Klp + (size_t)((kt + 1) * AK + key) * EMB + g4 * 4);
                uint32_t off = key * 128 + g4 * 8;
                uint32_t sw  = off ^ ((off >> 3) & 0x70);
                *(uint2*)(smem + kst + sw)         = khv;
                *(uint2*)(smem + kst + 16384 + sw) = klv;
            }
        }

        // ---- wait S(kt), read S ----
        MBAR_WAIT(MBS, kt & 1);
        TC_FENCE_AFTER();
        uint32_t s0[32], s1[32];
        LDTM_X32(s0, tm_s + half * 64);
        LDTM_X32(s1, tm_s + half * 64 + 32);
        TC_WAIT_LD();
        TC_FENCE_BEFORE();

        // ---- online softmax (base-2); lane owns one q-row ----
        float lmax = -__int_as_float(0x7f800000);
#pragma unroll
        for (int j = 0; j < 32; j++) {
            lmax = fmaxf(lmax, __uint_as_float(s0[j]));
            lmax = fmaxf(lmax, __uint_as_float(s1[j]));
        }
        halfmax[half * 128 + row] = lmax;
        __syncthreads();
        float mtile = fmaxf(lmax, halfmax[(half ^ 1) * 128 + row]);
        float mnew  = fmaxf(m, mtile);
        float corr  = ex2f(m - mnew);
        float psum  = 0.f;
        float p0[32], p1[32];
#pragma unroll
        for (int j = 0; j < 32; j++) {
            p0[j] = ex2f(__uint_as_float(s0[j]) - mnew);
            p1[j] = ex2f(__uint_as_float(s1[j]) - mnew);
            psum += p0[j] + p1[j];
        }
        halfsum[half * 128 + row] = psum;
        // ---- store P (split) to blocked smem ----
        {
            uint32_t base = (uint32_t)half * 16384 + (row >> 3) * 1024 + (row & 7) * 128;
#pragma unroll
            for (int j = 0; j < 16; j++) {
                __nv_bfloat16 h0 = __float2bfloat16(p0[2*j]);
                __nv_bfloat16 h1 = __float2bfloat16(p0[2*j+1]);
                __nv_bfloat16 h2 = __float2bfloat16(p1[2*j]);
                __nv_bfloat16 h3 = __float2bfloat16(p1[2*j+1]);
                __nv_bfloat16 l0 = __float2bfloat16(p0[2*j]   - __bfloat162float(h0));
                __nv_bfloat16 l1 = __float2bfloat16(p0[2*j+1] - __bfloat162float(h1));
                __nv_bfloat16 l2 = __float2bfloat16(p1[2*j]   - __bfloat162float(h2));
                __nv_bfloat16 l3 = __float2bfloat16(p1[2*j+1] - __bfloat162float(h3));
                uint32_t off  = base + j * 4;
                uint32_t sw   = off  ^ ((off  >> 3) & 0x70);
                uint32_t off2 = base + 64 + j * 4;
                uint32_t sw2  = off2 ^ ((off2 >> 3) & 0x70);
                *(uint32_t*)(smem + A_PH + sw)  = pk2(h0, h1);
                *(uint32_t*)(smem + A_PL + sw)  = pk2(l0, l1);
                *(uint32_t*)(smem + A_PH + sw2) = pk2(h2, h3);
                *(uint32_t*)(smem + A_PL + sw2) = pk2(l2, l3);
            }
        }
        FENCE_PROXY();
        __syncthreads();

        l = l * corr + halfsum[0 * 128 + row] + halfsum[1 * 128 + row];
        m = mnew;
#pragma unroll
        for (int j = 0; j < 32; j++) o_acc[j] *= corr;

        // ---- issue PV(kt) and S(kt+1) back-to-back ----
        if (wid == 0 && elect_one()) {
            TC_FENCE_AFTER();
#pragma unroll
            for (int ks = 0; ks < 8; ks++) {
                uint64_t po = (uint64_t)((ks >> 2) * 1024 + (ks & 3) * 2);
                uint64_t vo = (uint64_t)((ks >> 2) * 512  + (ks & 3) * 2);
                mma_f16_ss(tm_o, dPh + po, dVh + vo, IDESC_PV, ks != 0);
                mma_f16_ss(tm_o, dPh + po, dVl + vo, IDESC_PV, 1u);
                mma_f16_ss(tm_o, dPl + po, dVh + vo, IDESC_PV, 1u);
            }
            TC_COMMIT(MBP);
            if (kt + 1 < NT) {
                const int nb = (kt + 1) & 1;
#pragma unroll
                for (int ks = 0; ks < 4; ks++) {
                    mma_f16_ss(tm_s, dQh + ks * 2, dKh[nb] + ks * 2, GIDESC, ks != 0);
                    mma_f16_ss(tm_s, dQh + ks * 2, dKl[nb] + ks * 2, GIDESC, 1u);
                    mma_f16_ss(tm_s, dQl + ks * 2, dKh[nb] + ks * 2, GIDESC, 1u);
                }
                TC_COMMIT(MBS);
            }
        }

        // ---- wait PV(kt), accumulate ----
        MBAR_WAIT(MBP, kt & 1);
        TC_FENCE_AFTER();
        {
            uint32_t r[32];
            LDTM_X32(r, tm_o + half * 32);
            TC_WAIT_LD();
#pragma unroll
            for (int j = 0; j < 32; j++) o_acc[j] += __uint_as_float(r[j]);
        }
        TC_FENCE_BEFORE();
    }

    // ---- epilogue ----
    {
        float inv = 1.0f / l;
        float* Op = O + (rowbase + (size_t)qt * AQ + row) * EMB + h * HDIM + half * 32;
#pragma unroll
        for (int j = 0; j < 8; j++)
            *(float4*)(Op + j * 4) = make_float4(o_acc[4*j] * inv, o_acc[4*j+1] * inv,
                                                 o_acc[4*j+2] * inv, o_acc[4*j+3] * inv);
    }
    __syncthreads();
    if (wid == 0) { TC_RELINQ(); TC_DEALLOC(tmem, 256); }

#else  // ---------------- SIMT fallback attention (non-sm_103a) ---------------
    float* sm = (float*)smem;
    float (*Qts)[128]  = (float (*)[128])sm;
    float (*Vs)[64]    = (float (*)[64])(sm + 64*128);
    float (*Kts)[64]   = (float (*)[64])(sm + 64*128 + 64*64);
    float (*Pts)[128]  = (float (*)[128])(sm + 64*128 + 64*64);

    const int tx = t & 15, ty = t >> 4;
    const __nv_bfloat16* Qhp = Qh + (rowbase + (size_t)qt * 128) * EMB + h * HDIM;
    const __nv_bfloat16* Qlp = Ql + (rowbase + (size_t)qt * 128) * EMB + h * HDIM;
    const __nv_bfloat16* Khp = Kh + rowbase * EMB + h * HDIM;
    const __nv_bfloat16* Klp = Kl + rowbase * EMB + h * HDIM;
    const __nv_bfloat16* Vthp = Vth + ((size_t)b * 1024 + h * HDIM) * SEQ;
    const __nv_bfloat16* Vtlp = Vtl + ((size_t)b * 1024 + h * HDIM) * SEQ;

#pragma unroll
    for (int it = 0; it < 8; it++) {
        int idx  = it * 256 + t;
        int qrow = idx >> 4, cg = idx & 15;
#pragma unroll
        for (int u = 0; u < 4; u++) {
            int d = (cg << 2) + u;
            float qf = __bfloat162float(Qhp[(size_t)qrow * EMB + d])
                     + __bfloat162float(Qlp[(size_t)qrow * EMB + d]);
            int col = (((qrow >> 2) ^ cg) << 2) | (qrow & 3);
            Qts[d][col] = qf;   // pre-scaled
        }
    }

    float m[8], l[8], acc[8][4];
#pragma unroll
    for (int i = 0; i < 8; i++) {
        m[i] = -__int_as_float(0x7f800000); l[i] = 0.f;
#pragma unroll
        for (int dd = 0; dd < 4; dd++) acc[i][dd] = 0.f;
    }

    for (int kt = 0; kt < SEQ / 64; kt++) {
        __syncthreads();
#pragma unroll
        for (int it = 0; it < 4; it++) {
            int idx = it * 256 + t;
            int key = idx >> 4, cg = idx & 15;
#pragma unroll
            for (int u = 0; u < 4; u++) {
                int d = (cg << 2) + u;
                float kf = __bfloat162float(Khp[(size_t)(kt * 64 + key) * EMB + d])
                         + __bfloat162float(Klp[(size_t)(kt * 64 + key) * EMB + d]);
                int col = (((key >> 2) ^ cg) << 2) | (key & 3);
                Kts[d][col] = kf;
                Vs[key][d] = __bfloat162float(Vthp[(size_t)d * SEQ + kt * 64 + key])
                           + __bfloat162float(Vtlp[(size_t)d * SEQ + kt * 64 + key]);
            }
        }
        __syncthreads();

        float s_[8][4];
#pragma unroll
        for (int i = 0; i < 8; i++)
#pragma unroll
            for (int j = 0; j < 4; j++) s_[i][j] = 0.f;
#pragma unroll 8
        for (int d = 0; d < HDIM; d++) {
            int sw = (d >> 2) & 15;
            float4 k4 = *(const float4*)&Kts[d][(tx ^ sw) << 2];
            float4 q0 = *(const float4*)&Qts[d][((2 * ty) ^ sw) << 2];
            float4 q1 = *(const float4*)&Qts[d][((2 * ty + 1) ^ sw) << 2];
            float kf[4]  = {k4.x, k4.y, k4.z, k4.w};
            float q0f[4] = {q0.x, q0.y, q0.z, q0.w};
            float q1f[4] = {q1.x, q1.y, q1.z, q1.w};
#pragma unroll
            for (int i = 0; i < 4; i++)
#pragma unroll
                for (int j = 0; j < 4; j++) {
                    s_[i][j]     += q0f[i] * kf[j];
                    s_[4 + i][j] += q1f[i] * kf[j];
                }
        }

#pragma unroll
        for (int i = 0; i < 8; i++) {
            float mloc = fmaxf(fmaxf(s_[i][0], s_[i][1]), fmaxf(s_[i][2], s_[i][3]));
#pragma unroll
            for (int off = 8; off > 0; off >>= 1)
                mloc = fmaxf(mloc, __shfl_xor_sync(0xffffffffu, mloc, off, 16));
            float mnew = fmaxf(m[i], mloc);
            float corr = ex2f(m[i] - mnew);
            float rsum = 0.f;
#pragma unroll
            for (int j = 0; j < 4; j++) {
                float pv = ex2f(s_[i][j] - mnew);
                s_[i][j] = pv; rsum += pv;
            }
#pragma unroll
            for (int off = 8; off > 0; off >>= 1)
                rsum += __shfl_xor_sync(0xffffffffu, rsum, off, 16);
            l[i] = l[i] * corr + rsum; m[i] = mnew;
#pragma unroll
            for (int dd = 0; dd < 4; dd++) acc[i][dd] *= corr;
        }

        __syncthreads();
#pragma unroll
        for (int j = 0; j < 4; j++) {
            int key = (tx << 2) + j;
            int swp = key & 31;
            *(float4*)&Pts[key][((2 * ty) ^ swp) << 2] =
                make_float4(s_[0][j], s_[1][j], s_[2][j], s_[3][j]);
            *(float4*)&Pts[key][((2 * ty + 1) ^ swp) << 2] =
                make_float4(s_[4][j], s_[5][j], s_[6][j], s_[7][j]);
        }
        __syncthreads();

#pragma unroll 8
        for (int j = 0; j < 64; j++) {
            int swp = j & 31;
            float4 pp0 = *(const float4*)&Pts[j][((2 * ty) ^ swp) << 2];
            float4 pp1 = *(const float4*)&Pts[j][((2 * ty + 1) ^ swp) << 2];
            float4 v4 = *(const float4*)&Vs[j][tx << 2];
            float pf[8] = {pp0.x,pp0.y,pp0.z,pp0.w, pp1.x,pp1.y,pp1.z,pp1.w};
            float vf[4] = {v4.x, v4.y, v4.z, v4.w};
#pragma unroll
            for (int i = 0; i < 8; i++)
#pragma unroll
                for (int dd = 0; dd < 4; dd++)
                    acc[i][dd] += pf[i] * vf[dd];
        }
    }

#pragma unroll
    for (int i = 0; i < 8; i++) {
        float inv = 1.0f / l[i];
        int r = qt * 128 + (ty << 3) + i;
        *(float4*)(O + (rowbase + r) * EMB + h * HDIM + (tx << 2)) =
            make_float4(acc[i][0]*inv, acc[i][1]*inv, acc[i][2]*inv, acc[i][3]*inv);
    }
#endif
}

// ---------------------------------------------------------------------------
extern "C" void kernel_launch(void* const* d_in, const int* in_sizes, int n_in,
                              void* d_out, int out_size) {
    const float* query = (const float*)d_in[0];
    const float* key   = (const float*)d_in[1];
    const float* value = (const float*)d_in[2];
    const float* Wq    = (const float*)d_in[3];
    const float* Wk    = (const float*)d_in[4];
    const float* Wv    = (const float*)d_in[5];
    const float* Wo    = (const float*)d_in[6];
    float* out = (float*)d_out;

    __nv_bfloat16 *qh, *ql, *kh, *kl, *vth, *vtl;
    float *ctx;
    cudaGetSymbolAddress((void**)&qh,  g_qh);
    cudaGetSymbolAddress((void**)&ql,  g_ql);
    cudaGetSymbolAddress((void**)&kh,  g_kh);
    cudaGetSymbolAddress((void**)&kl,  g_kl);
    cudaGetSymbolAddress((void**)&vth, g_vth);
    cudaGetSymbolAddress((void**)&vtl, g_vtl);
    cudaGetSymbolAddress((void**)&ctx, g_ctx);

    cudaFuncSetAttribute(gemm_tc_kernel,
                         cudaFuncAttributeMaxDynamicSharedMemorySize, GSMEM);
    cudaFuncSetAttribute(attention_kernel,
                         cudaFuncAttributeMaxDynamicSharedMemorySize, ASMEM);

    const float qscale = 0.125f * 1.44269504088896340736f;
    dim3 gg(EMB / 128, MTOT / 128);
    gemm_tc_kernel<<<gg, 256, GSMEM>>>(query, Wq, nullptr, qh, ql, GM_SPLIT, qscale);
    gemm_tc_kernel<<<gg, 256, GSMEM>>>(key,   Wk, nullptr, kh, kl, GM_SPLIT, 1.0f);
    gemm_tc_kernel<<<gg, 256, GSMEM>>>(value, Wv, nullptr, vth, vtl, GM_SPLITT, 1.0f);
    attention_kernel<<<dim3(SEQ / AQ, NHEAD, BATCH), 256, ASMEM>>>(qh, ql, kh, kl, vth, vtl, ctx);
    gemm_tc_kernel<<<gg, 256, GSMEM>>>(ctx, Wo, out, nullptr, nullptr, GM_F32, 1.0f);
}

// round 17
// speedup vs baseline: 1.0691x; 1.0691x over previous
#include <cuda_runtime.h>
#include <cuda_bf16.h>
#include <cstdint>

#define EMB   1024
#define NHEAD 16
#define HDIM  64
#define BATCH 4
#define SEQ   2048
#define MTOT  (BATCH*SEQ)

// GEMM tensor-core config
#define GKC        64
#define TILE_B     16384
#define STAGE_B    (4*TILE_B)
#define GSMEM      (1024 + 2*STAGE_B) // 132096 bytes

// Attention config
#define AQ 128
#define AK 128
#define NT (SEQ/AK)
// attention smem (bytes): single K (hi+lo), V (hi+lo). 68,608 B -> 2 CTAs/SM.
#define A_HMAX    64
#define A_HSUM    1088
#define A_KH      3072
#define A_KL      (A_KH + 16384)
#define A_VH      (A_KL + 16384)
#define A_VL      (A_VH + 16384)
#define ASMEM     (A_VL + 16384)   // 68608

// GEMM output modes
#define GM_F32    0
#define GM_SPLIT  1
#define GM_SPLITT 2

// Scratch (device-global: allocation-guard-safe)
__device__ __nv_bfloat16 g_qh[MTOT*EMB];
__device__ __nv_bfloat16 g_ql[MTOT*EMB];
__device__ __nv_bfloat16 g_kh[MTOT*EMB];
__device__ __nv_bfloat16 g_kl[MTOT*EMB];
__device__ __nv_bfloat16 g_vth[MTOT*EMB];
__device__ __nv_bfloat16 g_vtl[MTOT*EMB];
__device__ float g_ctx[MTOT*EMB];

__device__ __forceinline__ float ex2f(float x) {
    float y; asm("ex2.approx.ftz.f32 %0, %1;" : "=f"(y) : "f"(x)); return y;
}

#if defined(__CUDA_ARCH_FEAT_SM103_ALL) || !defined(__CUDA_ARCH__)
#define HAS_TCGEN05 1
#else
#define HAS_TCGEN05 0
#endif

#if HAS_TCGEN05
// ---------------- tcgen05 helpers (parsed on host; emitted only on sm_103a) ----
__device__ __forceinline__ uint32_t elect_one() {
    uint32_t pr;
    asm volatile("{\n\t.reg .pred p;\n\telect.sync _|p, 0xFFFFFFFF;\n\t"
                 "selp.b32 %0, 1, 0, p;\n\t}" : "=r"(pr));
    return pr;
}
__device__ __forceinline__ uint64_t mkdesc(uint32_t addr) {  // SW128 K-major, LBO=1, SBO=64
    const uint64_t base = (uint64_t(2) << 61) | (uint64_t(1) << 46)
                        | (uint64_t(64) << 32) | (uint64_t(1) << 16);
    return base | ((uint64_t)(addr >> 4) & 0x3FFF);
}
__device__ __forceinline__ void mma_f16_ss(uint32_t d, uint64_t ad, uint64_t bd,
                                           uint32_t idesc, uint32_t en) {
    asm volatile("{\n\t.reg .pred p;\n\tsetp.ne.u32 p, %5, 0;\n\t"
        "tcgen05.mma.cta_group::1.kind::f16 [%0], %1, %2, %3, {%4,%4,%4,%4}, p;\n\t}"
        :: "r"(d), "l"(ad), "l"(bd), "r"(idesc), "r"(0u), "r"(en) : "memory");
}
__device__ __forceinline__ void mma_f16_ts(uint32_t d, uint32_t a_tmem, uint64_t bd,
                                           uint32_t idesc, uint32_t en) {
    asm volatile("{\n\t.reg .pred p;\n\tsetp.ne.u32 p, %5, 0;\n\t"
        "tcgen05.mma.cta_group::1.kind::f16 [%0], [%1], %2, %3, {%4,%4,%4,%4}, p;\n\t}"
        :: "r"(d), "r"(a_tmem), "l"(bd), "r"(idesc), "r"(0u), "r"(en) : "memory");
}
#define TC_COMMIT(a) \
    asm volatile("tcgen05.commit.cta_group::1.mbarrier::arrive::one.shared::cluster.b64 [%0];" \
                 :: "r"(a) : "memory")
#define TC_ALLOC(sres, n) \
    asm volatile("tcgen05.alloc.cta_group::1.sync.aligned.shared::cta.b32 [%0], %1;" \
                 :: "r"(sres), "r"((uint32_t)(n)) : "memory")
#define TC_DEALLOC(tm, n) \
    asm volatile("tcgen05.dealloc.cta_group::1.sync.aligned.b32 %0, %1;" :: "r"(tm), "r"((uint32_t)(n)))
#define TC_RELINQ() asm volatile("tcgen05.relinquish_alloc_permit.cta_group::1.sync.aligned;")
#define TC_FENCE_AFTER()  asm volatile("tcgen05.fence::after_thread_sync;" ::: "memory")
#define TC_FENCE_BEFORE() asm volatile("tcgen05.fence::before_thread_sync;" ::: "memory")
#define TC_WAIT_LD() asm volatile("tcgen05.wait::ld.sync.aligned;" ::: "memory")
#define TC_WAIT_ST() asm volatile("tcgen05.wait::st.sync.aligned;" ::: "memory")
#define LDTM_X32(r, a) \
    asm volatile("tcgen05.ld.sync.aligned.32x32b.x32.b32 "                        \
        "{%0,%1,%2,%3,%4,%5,%6,%7,%8,%9,%10,%11,%12,%13,%14,%15,"                 \
        "%16,%17,%18,%19,%20,%21,%22,%23,%24,%25,%26,%27,%28,%29,%30,%31}, [%32];"\
        : "=r"((r)[0]),"=r"((r)[1]),"=r"((r)[2]),"=r"((r)[3]),                    \
          "=r"((r)[4]),"=r"((r)[5]),"=r"((r)[6]),"=r"((r)[7]),                    \
          "=r"((r)[8]),"=r"((r)[9]),"=r"((r)[10]),"=r"((r)[11]),                  \
          "=r"((r)[12]),"=r"((r)[13]),"=r"((r)[14]),"=r"((r)[15]),                \
          "=r"((r)[16]),"=r"((r)[17]),"=r"((r)[18]),"=r"((r)[19]),                \
          "=r"((r)[20]),"=r"((r)[21]),"=r"((r)[22]),"=r"((r)[23]),                \
          "=r"((r)[24]),"=r"((r)[25]),"=r"((r)[26]),"=r"((r)[27]),                \
          "=r"((r)[28]),"=r"((r)[29]),"=r"((r)[30]),"=r"((r)[31])                 \
        : "r"(a))
#define STTM_X32(a, r) \
    asm volatile("tcgen05.st.sync.aligned.32x32b.x32.b32 [%0], "                  \
        "{%1,%2,%3,%4,%5,%6,%7,%8,%9,%10,%11,%12,%13,%14,%15,%16,"                \
        "%17,%18,%19,%20,%21,%22,%23,%24,%25,%26,%27,%28,%29,%30,%31,%32};"       \
        :: "r"(a),                                                                \
           "r"((r)[0]),"r"((r)[1]),"r"((r)[2]),"r"((r)[3]),                       \
           "r"((r)[4]),"r"((r)[5]),"r"((r)[6]),"r"((r)[7]),                       \
           "r"((r)[8]),"r"((r)[9]),"r"((r)[10]),"r"((r)[11]),                     \
           "r"((r)[12]),"r"((r)[13]),"r"((r)[14]),"r"((r)[15]),                   \
           "r"((r)[16]),"r"((r)[17]),"r"((r)[18]),"r"((r)[19]),                   \
           "r"((r)[20]),"r"((r)[21]),"r"((r)[22]),"r"((r)[23]),                   \
           "r"((r)[24]),"r"((r)[25]),"r"((r)[26]),"r"((r)[27]),                   \
           "r"((r)[28]),"r"((r)[29]),"r"((r)[30]),"r"((r)[31])                    \
        : "memory")
#endif // HAS_TCGEN05 helpers

// ---- arch-independent helpers ----
__device__ __forceinline__ uint32_t smem_u32(const void* p) {
    uint32_t a;
    asm("{ .reg .u64 t; cvta.to.shared.u64 t, %1; cvt.u32.u64 %0, t; }"
        : "=r"(a) : "l"(p));
    return a;
}
#define MBAR_INIT(a, n) \
    asm volatile("mbarrier.init.shared.b64 [%0], %1;" :: "r"(a), "r"(n) : "memory")
#define MBAR_WAIT(a, par) do {                                                    \
    uint32_t _m = (a), _p = (par), _d;                                            \
    asm volatile("{\n\t.reg .pred p;\n\t"                                         \
        "mbarrier.try_wait.parity.acquire.cta.shared::cta.b64 p, [%1], %2;\n\t"   \
        "selp.b32 %0, 1, 0, p;\n\t}" : "=r"(_d) : "r"(_m), "r"(_p) : "memory");   \
    if (!_d) {                                                                    \
        asm volatile("{\n\t.reg .pred P1;\n\tWL_%=:\n\t"                          \
            "mbarrier.try_wait.parity.acquire.cta.shared::cta.b64 P1, [%0], %1, 0x989680;\n\t" \
            "@P1 bra.uni WD_%=;\n\tbra.uni WL_%=;\n\tWD_%=:\n\t}"                 \
            :: "r"(_m), "r"(_p) : "memory");                                      \
    } } while (0)
#define FENCE_PROXY() asm volatile("fence.proxy.async.shared::cta;" ::: "memory")

__device__ __forceinline__ uint32_t pk2(__nv_bfloat16 lo, __nv_bfloat16 hi) {
    return (uint32_t)__bfloat16_as_ushort(lo) | ((uint32_t)__bfloat16_as_ushort(hi) << 16);
}

// idescs: F32 acc, BF16 a/b, M=128
#define GIDESC   ((1u<<4)|(1u<<7)|(1u<<10)|((128u/8)<<17)|((128u/16)<<24))  // N=128
#define IDESC_PV ((1u<<4)|(1u<<7)|(1u<<10)|(( 64u/8)<<17)|((128u/16)<<24))  // N=64

// ---------------------------------------------------------------------------
// C = A[M,K] * W[N,K]^T, output mode selects fp32 / split-bf16 / split-transposed.
// (unchanged — validated)
// ---------------------------------------------------------------------------
__global__ void __launch_bounds__(256, 1)
gemm_tc_kernel(const float* __restrict__ A, const float* __restrict__ W,
               float* __restrict__ C,
               __nv_bfloat16* __restrict__ Ch, __nv_bfloat16* __restrict__ Cl,
               int mode, float oscale) {
    extern __shared__ __align__(1024) char smem[];
    const int t = threadIdx.x;
    const int bm = blockIdx.y << 7, bn = blockIdx.x << 7;

#if HAS_TCGEN05
    const uint32_t sb = smem_u32(smem);
    const int wid = t >> 5, lane = t & 31;
    const uint32_t TMP   = sb;
    const uint32_t MB0   = sb + 16;
    const uint32_t MB1   = sb + 24;
    const uint32_t TILES = sb + 1024;

    if (t == 0) { MBAR_INIT(MB0, 1); MBAR_INIT(MB1, 1); }
    if (wid == 0) TC_ALLOC(TMP, 128);
    __syncthreads();
    uint32_t tmem;
    asm volatile("ld.shared.b32 %0, [%1];" : "=r"(tmem) : "r"(TMP));

    int ph0 = 0, ph1 = 0;

    for (int c = 0; c < EMB / GKC; c++) {
        const int buf = c & 1;
        if (c >= 2) {
            if (buf == 0) { MBAR_WAIT(MB0, ph0 & 1); ph0++; }
            else          { MBAR_WAIT(MB1, ph1 & 1); ph1++; }
        }
        const uint32_t stage = TILES + buf * STAGE_B;
#pragma unroll
        for (int it = 0; it < 8; it++) {
            int idx = it * 256 + t;
            int row = idx >> 4, g4 = idx & 15;
            float4 av = *(const float4*)(A + (size_t)(bm + row) * EMB + c * GKC + g4 * 4);
            float4 wv = *(const float4*)(W + (size_t)(bn + row) * EMB + c * GKC + g4 * 4);
            uint32_t off = row * 128 + g4 * 8;
            uint32_t sw  = off ^ ((off >> 3) & 0x70);
            float af[4] = {av.x, av.y, av.z, av.w};
            float wf[4] = {wv.x, wv.y, wv.z, wv.w};
            __nv_bfloat16 ah[4], al[4], wh[4], wl[4];
#pragma unroll
            for (int u = 0; u < 4; u++) {
                ah[u] = __float2bfloat16(af[u]);
                al[u] = __float2bfloat16(af[u] - __bfloat162float(ah[u]));
                wh[u] = __float2bfloat16(wf[u]);
                wl[u] = __float2bfloat16(wf[u] - __bfloat162float(wh[u]));
            }
            char* stp = smem + (stage - sb);
            *(uint2*)(stp + 0 * TILE_B + sw) = make_uint2(pk2(ah[0], ah[1]), pk2(ah[2], ah[3]));
            *(uint2*)(stp + 1 * TILE_B + sw) = make_uint2(pk2(al[0], al[1]), pk2(al[2], al[3]));
            *(uint2*)(stp + 2 * TILE_B + sw) = make_uint2(pk2(wh[0], wh[1]), pk2(wh[2], wh[3]));
            *(uint2*)(stp + 3 * TILE_B + sw) = make_uint2(pk2(wl[0], wl[1]), pk2(wl[2], wl[3]));
        }
        FENCE_PROXY();
        __syncthreads();

        if (wid == 0 && elect_one()) {
            uint64_t dAh = mkdesc(stage + 0 * TILE_B);
            uint64_t dAl = mkdesc(stage + 1 * TILE_B);
            uint64_t dBh = mkdesc(stage + 2 * TILE_B);
            uint64_t dBl = mkdesc(stage + 3 * TILE_B);
#pragma unroll
            for (int ks = 0; ks < 4; ks++) {
                uint32_t en0 = !(c == 0 && ks == 0);
                mma_f16_ss(tmem, dAh + ks * 2, dBh + ks * 2, GIDESC, en0);
                mma_f16_ss(tmem, dAh + ks * 2, dBl + ks * 2, GIDESC, 1u);
                mma_f16_ss(tmem, dAl + ks * 2, dBh + ks * 2, GIDESC, 1u);
            }
            TC_COMMIT(buf ? MB1 : MB0);
        }
    }

    MBAR_WAIT(MB0, ph0 & 1);
    MBAR_WAIT(MB1, ph1 & 1);
    TC_FENCE_AFTER();

    {
        const int half = wid >> 2, sub = wid & 3;
        const int row = bm + sub * 32 + lane;
#pragma unroll
        for (int cb = 0; cb < 2; cb++) {
            uint32_t col = (uint32_t)(half * 64 + cb * 32);
            uint32_t r[32];
            LDTM_X32(r, tmem + col);
            TC_WAIT_LD();
            if (mode == GM_F32) {
                float* Cp = C + (size_t)row * EMB + bn + col;
#pragma unroll
                for (int j = 0; j < 8; j++) {
                    *(float4*)(Cp + j * 4) = make_float4(
                        __uint_as_float(r[4 * j + 0]), __uint_as_float(r[4 * j + 1]),
                        __uint_as_float(r[4 * j + 2]), __uint_as_float(r[4 * j + 3]));
                }
            } else if (mode == GM_SPLIT) {
                __nv_bfloat16* Hp = Ch + (size_t)row * EMB + bn + col;
                __nv_bfloat16* Lp = Cl + (size_t)row * EMB + bn + col;
#pragma unroll
                for (int j4 = 0; j4 < 8; j4++) {
                    __nv_bfloat16 hh[4], ll[4];
#pragma unroll
                    for (int u = 0; u < 4; u++) {
                        float f = __uint_as_float(r[4 * j4 + u]) * oscale;
                        hh[u] = __float2bfloat16(f);
                        ll[u] = __float2bfloat16(f - __bfloat162float(hh[u]));
                    }
                    *(uint2*)(Hp + j4 * 4) = make_uint2(pk2(hh[0], hh[1]), pk2(hh[2], hh[3]));
                    *(uint2*)(Lp + j4 * 4) = make_uint2(pk2(ll[0], ll[1]), pk2(ll[2], ll[3]));
                }
            } else {  // GM_SPLITT
                const int bb = row >> 11, s = row & 2047;
#pragma unroll
                for (int j = 0; j < 32; j++) {
                    int colg = bn + (int)col + j;
                    float f = __uint_as_float(r[j]);
                    __nv_bfloat16 hv = __float2bfloat16(f);
                    __nv_bfloat16 lv = __float2bfloat16(f - __bfloat162float(hv));
                    size_t dst = ((size_t)bb * 1024 + colg) * SEQ + s;
                    Ch[dst] = hv;
                    Cl[dst] = lv;
                }
            }
        }
        TC_FENCE_BEFORE();
    }
    __syncthreads();
    if (wid == 0) { TC_RELINQ(); TC_DEALLOC(tmem, 128); }

#else  // ---------------- SIMT fallback (non-sm_103a device binaries) ---------
    float* As = (float*)smem;
    float* Bs = (float*)smem + 8 * 128;
    const int tx = t & 15, ty = t >> 4;
    const int lrow = t >> 1, lk = (t & 1) << 2;
    const float* Ap = A + (size_t)(bm + lrow) * EMB + lk;
    const float* Wp = W + (size_t)(bn + lrow) * EMB + lk;

    float acc[8][8];
#pragma unroll
    for (int i = 0; i < 8; i++)
#pragma unroll
        for (int j = 0; j < 8; j++) acc[i][j] = 0.f;

    for (int k0 = 0; k0 < EMB; k0 += 8) {
        float4 av = *(const float4*)(Ap + k0);
        float4 wv = *(const float4*)(Wp + k0);
        __syncthreads();
        As[(lk+0)*128+lrow] = av.x; As[(lk+1)*128+lrow] = av.y;
        As[(lk+2)*128+lrow] = av.z; As[(lk+3)*128+lrow] = av.w;
        Bs[(lk+0)*128+lrow] = wv.x; Bs[(lk+1)*128+lrow] = wv.y;
        Bs[(lk+2)*128+lrow] = wv.z; Bs[(lk+3)*128+lrow] = wv.w;
        __syncthreads();
#pragma unroll
        for (int kk = 0; kk < 8; kk++) {
            float4 a0 = *(const float4*)&As[kk*128 + (ty << 2)];
            float4 a1 = *(const float4*)&As[kk*128 + 64 + (ty << 2)];
            float4 b0 = *(const float4*)&Bs[kk*128 + (tx << 2)];
            float4 b1 = *(const float4*)&Bs[kk*128 + 64 + (tx << 2)];
            float ar[8] = {a0.x,a0.y,a0.z,a0.w, a1.x,a1.y,a1.z,a1.w};
            float br[8] = {b0.x,b0.y,b0.z,b0.w, b1.x,b1.y,b1.z,b1.w};
#pragma unroll
            for (int i = 0; i < 8; i++)
#pragma unroll
                for (int j = 0; j < 8; j++)
                    acc[i][j] += ar[i] * br[j];
        }
    }
#pragma unroll
    for (int i = 0; i < 8; i++) {
        int r = bm + ((i < 4) ? ((ty << 2) + i) : (64 + (ty << 2) + i - 4));
#pragma unroll
        for (int jj = 0; jj < 8; jj++) {
            int colg = bn + ((jj < 4) ? (tx << 2) + jj : 64 + (tx << 2) + jj - 4);
            float f = acc[i][jj];
            if (mode == GM_F32) {
                C[(size_t)r * EMB + colg] = f;
            } else if (mode == GM_SPLIT) {
                f *= oscale;
                __nv_bfloat16 hv = __float2bfloat16(f);
                Ch[(size_t)r * EMB + colg] = hv;
                Cl[(size_t)r * EMB + colg] = __float2bfloat16(f - __bfloat162float(hv));
            } else {
                __nv_bfloat16 hv = __float2bfloat16(f);
                size_t dst = ((size_t)(r >> 11) * 1024 + colg) * SEQ + (r & 2047);
                Ch[dst] = hv;
                Cl[dst] = __float2bfloat16(f - __bfloat162float(hv));
            }
        }
    }
#endif
}

// ---------------------------------------------------------------------------
// Tensor-core flash attention, 2 CTAs/SM target.
// Q (split) and P (split) live in TMEM (TS-mode MMAs); K/V split in smem.
// PV = 3 TS-mode MMAs (Ph·Vh + Ph·Vl + Pl·Vh) — only Pl·Vl dropped (~2^-18).
// ---------------------------------------------------------------------------
__global__ void __launch_bounds__(256, 2)
attention_kernel(const __nv_bfloat16* __restrict__ Qh, const __nv_bfloat16* __restrict__ Ql,
                 const __nv_bfloat16* __restrict__ Kh, const __nv_bfloat16* __restrict__ Kl,
                 const __nv_bfloat16* __restrict__ Vth, const __nv_bfloat16* __restrict__ Vtl,
                 float* __restrict__ O) {
    extern __shared__ __align__(1024) char smem[];
    const int t = threadIdx.x;
    const int qt = blockIdx.x, h = blockIdx.y, b = blockIdx.z;
    const size_t rowbase = (size_t)b * SEQ;

#if HAS_TCGEN05
    const uint32_t sb = smem_u32(smem);
    const int wid = t >> 5, lane = t & 31;
    const int sub = wid & 3, half = wid >> 2;
    const int row = sub * 32 + lane;

    const uint32_t TMP = sb;
    const uint32_t MBS = sb + 16;
    const uint32_t MBP = sb + 24;
    float* halfmax = (float*)(smem + A_HMAX);
    float* halfsum = (float*)(smem + A_HSUM);

    if (t == 0) { MBAR_INIT(MBS, 1); MBAR_INIT(MBP, 1); }
    if (wid == 0) TC_ALLOC(TMP, 512);
    __syncthreads();
    uint32_t tmem;
    asm volatile("ld.shared.b32 %0, [%1];" : "=r"(tmem) : "r"(TMP));
    const uint32_t tm_s  = tmem;          // S: cols 0-127
    const uint32_t tm_o  = tmem + 128;    // O: cols 128-191
    const uint32_t tm_qh = tmem + 192;    // Q hi: cols 192-223
    const uint32_t tm_ql = tmem + 224;    // Q lo: cols 224-255
    const uint32_t tm_ph = tmem + 256;    // P hi: cols 256-319
    const uint32_t tm_pl = tmem + 320;    // P lo: cols 320-383

    const __nv_bfloat16* Qhp = Qh + (rowbase + (size_t)qt * AQ) * EMB + h * HDIM;
    const __nv_bfloat16* Qlp = Ql + (rowbase + (size_t)qt * AQ) * EMB + h * HDIM;
    const __nv_bfloat16* Khp = Kh + rowbase * EMB + h * HDIM;
    const __nv_bfloat16* Klp = Kl + rowbase * EMB + h * HDIM;
    const __nv_bfloat16* Vthp = Vth + ((size_t)b * 1024 + h * HDIM) * SEQ;
    const __nv_bfloat16* Vtlp = Vtl + ((size_t)b * 1024 + h * HDIM) * SEQ;

    // ---- Q (pre-scaled split bf16) -> TMEM, lane = q-row (warps 0-3) ----
    if (wid < 4) {
        uint32_t qr[32];
        const uint32_t woff = (uint32_t)(wid << 21);
        const __nv_bfloat16* qp = Qhp + (size_t)t * EMB;
#pragma unroll
        for (int j = 0; j < 8; j++) {
            uint4 v = *(const uint4*)(qp + j * 8);
            qr[4*j] = v.x; qr[4*j+1] = v.y; qr[4*j+2] = v.z; qr[4*j+3] = v.w;
        }
        STTM_X32(tm_qh + woff, qr);
        qp = Qlp + (size_t)t * EMB;
#pragma unroll
        for (int j = 0; j < 8; j++) {
            uint4 v = *(const uint4*)(qp + j * 8);
            qr[4*j] = v.x; qr[4*j+1] = v.y; qr[4*j+2] = v.z; qr[4*j+3] = v.w;
        }
        STTM_X32(tm_ql + woff, qr);
        TC_WAIT_ST();
    }
    TC_FENCE_BEFORE();
    __syncthreads();

    const uint64_t dKh = mkdesc(sb + A_KH);
    const uint64_t dKl = mkdesc(sb + A_KL);
    const uint64_t dVh = mkdesc(sb + A_VH);
    const uint64_t dVl = mkdesc(sb + A_VL);

    float m = -__int_as_float(0x7f800000);
    float l = 0.f;
    float o_acc[32];
#pragma unroll
    for (int j = 0; j < 32; j++) o_acc[j] = 0.f;

    // V-store assignment (validated R12): thread owns (d = t>>2, keys [kg*32,+32))
    const int vd = t >> 2, vkg = t & 3;
    const uint32_t vbase = (uint32_t)((vkg >> 1) * 8192 + (vd >> 3) * 1024
                                    + (vd & 7) * 128 + (vkg & 1) * 64);
    const __nv_bfloat16* VthD = Vthp + (size_t)vd * SEQ;
    const __nv_bfloat16* VtlD = Vtlp + (size_t)vd * SEQ;

    for (int kt = 0; kt < NT; kt++) {
        // ---- load K(kt) hi+lo and V(kt) hi+lo (pure copies) ----
#pragma unroll
        for (int it = 0; it < 8; it++) {
            int idx = it * 256 + t;
            int key = idx >> 4, g4 = idx & 15;
            uint2 khv = *(const uint2*)(Khp + (size_t)(kt * AK + key) * EMB + g4 * 4);
            uint2 klv = *(const uint2*)(Klp + (size_t)(kt * AK + key) * EMB + g4 * 4);
            uint32_t off = key * 128 + g4 * 8;
            uint32_t sw  = off ^ ((off >> 3) & 0x70);
            *(uint2*)(smem + A_KH + sw) = khv;
            *(uint2*)(smem + A_KL + sw) = klv;
        }
#pragma unroll
        for (int j = 0; j < 8; j++) {
            int koff = kt * AK + vkg * 32 + 4 * j;
            uint2 hv = *(const uint2*)(VthD + koff);
            uint2 lv = *(const uint2*)(VtlD + koff);
            uint32_t off = vbase + j * 8;
            uint32_t sw  = off ^ ((off >> 3) & 0x70);
            *(uint2*)(smem + A_VH + sw) = hv;
            *(uint2*)(smem + A_VL + sw) = lv;
        }
        FENCE_PROXY();
        __syncthreads();

        // ---- S = Q·K^T (TS mode: Q in TMEM), 12 dispatches ----
        if (wid == 0 && elect_one()) {
            TC_FENCE_AFTER();
#pragma unroll
            for (int ks = 0; ks < 4; ks++) {
                mma_f16_ts(tm_s, tm_qh + ks * 8, dKh + ks * 2, GIDESC, ks != 0);
                mma_f16_ts(tm_s, tm_qh + ks * 8, dKl + ks * 2, GIDESC, 1u);
                mma_f16_ts(tm_s, tm_ql + ks * 8, dKh + ks * 2, GIDESC, 1u);
            }
            TC_COMMIT(MBS);
        }
        MBAR_WAIT(MBS, kt & 1);
        TC_FENCE_AFTER();

        uint32_t s0[32], s1[32];
        LDTM_X32(s0, tm_s + half * 64);
        LDTM_X32(s1, tm_s + half * 64 + 32);
        TC_WAIT_LD();
        TC_FENCE_BEFORE();

        // ---- online softmax (base-2); lane owns one q-row; p in place ----
        float lmax = -__int_as_float(0x7f800000);
#pragma unroll
        for (int j = 0; j < 32; j++) {
            lmax = fmaxf(lmax, __uint_as_float(s0[j]));
            lmax = fmaxf(lmax, __uint_as_float(s1[j]));
        }
        halfmax[half * 128 + row] = lmax;
        __syncthreads();
        float mtile = fmaxf(lmax, halfmax[(half ^ 1) * 128 + row]);
        float mnew  = fmaxf(m, mtile);
        float corr  = ex2f(m - mnew);
        float psum  = 0.f;
#pragma unroll
        for (int j = 0; j < 32; j++) {
            float a  = ex2f(__uint_as_float(s0[j]) - mnew);
            float c2 = ex2f(__uint_as_float(s1[j]) - mnew);
            s0[j] = __float_as_uint(a);
            s1[j] = __float_as_uint(c2);
            psum += a + c2;
        }
        halfsum[half * 128 + row] = psum;

        // ---- P split -> TMEM (this warp's 32 cols: keys half*64..+63) ----
        {
            uint32_t phr[32], plr[32];
#pragma unroll
            for (int cc = 0; cc < 16; cc++) {
                float a = __uint_as_float(s0[2*cc]);
                float bqq = __uint_as_float(s0[2*cc+1]);
                __nv_bfloat16 ha = __float2bfloat16(a);
                __nv_bfloat16 hb = __float2bfloat16(bqq);
                phr[cc] = pk2(ha, hb);
                plr[cc] = pk2(__float2bfloat16(a - __bfloat162float(ha)),
                              __float2bfloat16(bqq - __bfloat162float(hb)));
            }
#pragma unroll
            for (int cc = 0; cc < 16; cc++) {
                float a = __uint_as_float(s1[2*cc]);
                float bqq = __uint_as_float(s1[2*cc+1]);
                __nv_bfloat16 ha = __float2bfloat16(a);
                __nv_bfloat16 hb = __float2bfloat16(bqq);
                phr[16 + cc] = pk2(ha, hb);
                plr[16 + cc] = pk2(__float2bfloat16(a - __bfloat162float(ha)),
                                   __float2bfloat16(bqq - __bfloat162float(hb)));
            }
            const uint32_t woff = (uint32_t)(sub << 21) + (uint32_t)(half * 32);
            STTM_X32(tm_ph + woff, phr);
            STTM_X32(tm_pl + woff, plr);
            TC_WAIT_ST();
        }
        TC_FENCE_BEFORE();
        __syncthreads();

        l = l * corr + halfsum[0 * 128 + row] + halfsum[1 * 128 + row];
        m = mnew;
#pragma unroll
        for (int j = 0; j < 32; j++) o_acc[j] *= corr;

        // ---- PV (TS mode: P in TMEM): 24 dispatches ----
        if (wid == 0 && elect_one()) {
            TC_FENCE_AFTER();
#pragma unroll
            for (int ks = 0; ks < 8; ks++) {
                uint32_t po = (uint32_t)(ks * 8);
                uint64_t vo = (uint64_t)((ks >> 2) * 512 + (ks & 3) * 2);
                mma_f16_ts(tm_o, tm_ph + po, dVh + vo, IDESC_PV, ks != 0);
                mma_f16_ts(tm_o, tm_ph + po, dVl + vo, IDESC_PV, 1u);
                mma_f16_ts(tm_o, tm_pl + po, dVh + vo, IDESC_PV, 1u);
            }
            TC_COMMIT(MBP);
        }
        MBAR_WAIT(MBP, kt & 1);
        TC_FENCE_AFTER();
        {
            uint32_t r[32];
            LDTM_X32(r, tm_o + half * 32);
            TC_WAIT_LD();
#pragma unroll
            for (int j = 0; j < 32; j++) o_acc[j] += __uint_as_float(r[j]);
        }
        TC_FENCE_BEFORE();
        __syncthreads();   // tile fully consumed before K/V/P overwrite
    }

    // ---- epilogue ----
    {
        float inv = 1.0f / l;
        float* Op = O + (rowbase + (size_t)qt * AQ + row) * EMB + h * HDIM + half * 32;
#pragma unroll
        for (int j = 0; j < 8; j++)
            *(float4*)(Op + j * 4) = make_float4(o_acc[4*j] * inv, o_acc[4*j+1] * inv,
                                                 o_acc[4*j+2] * inv, o_acc[4*j+3] * inv);
    }
    __syncthreads();
    if (wid == 0) { TC_RELINQ(); TC_DEALLOC(tmem, 512); }

#else  // ---------------- SIMT fallback attention (non-sm_103a) ---------------
    float* sm = (float*)smem;
    float (*Qts)[128]  = (float (*)[128])sm;
    float (*Vs)[64]    = (float (*)[64])(sm + 64*128);
    float (*Kts)[64]   = (float (*)[64])(sm + 64*128 + 64*64);
    float (*Pts)[128]  = (float (*)[128])(sm + 64*128 + 64*64);

    const int tx = t & 15, ty = t >> 4;
    const __nv_bfloat16* Qhp = Qh + (rowbase + (size_t)qt * 128) * EMB + h * HDIM;
    const __nv_bfloat16* Qlp = Ql + (rowbase + (size_t)qt * 128) * EMB + h * HDIM;
    const __nv_bfloat16* Khp = Kh + rowbase * EMB + h * HDIM;
    const __nv_bfloat16* Klp = Kl + rowbase * EMB + h * HDIM;
    const __nv_bfloat16* Vthp = Vth + ((size_t)b * 1024 + h * HDIM) * SEQ;
    const __nv_bfloat16* Vtlp = Vtl + ((size_t)b * 1024 + h * HDIM) * SEQ;

#pragma unroll
    for (int it = 0; it < 8; it++) {
        int idx  = it * 256 + t;
        int qrow = idx >> 4, cg = idx & 15;
#pragma unroll
        for (int u = 0; u < 4; u++) {
            int d = (cg << 2) + u;
            float qf = __bfloat162float(Qhp[(size_t)qrow * EMB + d])
                     + __bfloat162float(Qlp[(size_t)qrow * EMB + d]);
            int col = (((qrow >> 2) ^ cg) << 2) | (qrow & 3);
            Qts[d][col] = qf;
        }
    }

    float m[8], l[8], acc[8][4];
#pragma unroll
    for (int i = 0; i < 8; i++) {
        m[i] = -__int_as_float(0x7f800000); l[i] = 0.f;
#pragma unroll
        for (int dd = 0; dd < 4; dd++) acc[i][dd] = 0.f;
    }

    for (int kt = 0; kt < SEQ / 64; kt++) {
        __syncthreads();
#pragma unroll
        for (int it = 0; it < 4; it++) {
            int idx = it * 256 + t;
            int key = idx >> 4, cg = idx & 15;
#pragma unroll
            for (int u = 0; u < 4; u++) {
                int d = (cg << 2) + u;
                float kf = __bfloat162float(Khp[(size_t)(kt * 64 + key) * EMB + d])
                         + __bfloat162float(Klp[(size_t)(kt * 64 + key) * EMB + d]);
                int col = (((key >> 2) ^ cg) << 2) | (key & 3);
                Kts[d][col] = kf;
                Vs[key][d] = __bfloat162float(Vthp[(size_t)d * SEQ + kt * 64 + key])
                           + __bfloat162float(Vtlp[(size_t)d * SEQ + kt * 64 + key]);
            }
        }
        __syncthreads();

        float s_[8][4];
#pragma unroll
        for (int i = 0; i < 8; i++)
#pragma unroll
            for (int j = 0; j < 4; j++) s_[i][j] = 0.f;
#pragma unroll 8
        for (int d = 0; d < HDIM; d++) {
            int sw = (d >> 2) & 15;
            float4 k4 = *(const float4*)&Kts[d][(tx ^ sw) << 2];
            float4 q0 = *(const float4*)&Qts[d][((2 * ty) ^ sw) << 2];
            float4 q1 = *(const float4*)&Qts[d][((2 * ty + 1) ^ sw) << 2];
            float kf[4]  = {k4.x, k4.y, k4.z, k4.w};
            float q0f[4] = {q0.x, q0.y, q0.z, q0.w};
            float q1f[4] = {q1.x, q1.y, q1.z, q1.w};
#pragma unroll
            for (int i = 0; i < 4; i++)
#pragma unroll
                for (int j = 0; j < 4; j++) {
                    s_[i][j]     += q0f[i] * kf[j];
                    s_[4 + i][j] += q1f[i] * kf[j];
                }
        }

#pragma unroll
        for (int i = 0; i < 8; i++) {
            float mloc = fmaxf(fmaxf(s_[i][0], s_[i][1]), fmaxf(s_[i][2], s_[i][3]));
#pragma unroll
            for (int off = 8; off > 0; off >>= 1)
                mloc = fmaxf(mloc, __shfl_xor_sync(0xffffffffu, mloc, off, 16));
            float mnew = fmaxf(m[i], mloc);
            float corr = ex2f(m[i] - mnew);
            float rsum = 0.f;
#pragma unroll
            for (int j = 0; j < 4; j++) {
                float pv = ex2f(s_[i][j] - mnew);
                s_[i][j] = pv; rsum += pv;
            }
#pragma unroll
            for (int off = 8; off > 0; off >>= 1)
                rsum += __shfl_xor_sync(0xffffffffu, rsum, off, 16);
            l[i] = l[i] * corr + rsum; m[i] = mnew;
#pragma unroll
            for (int dd = 0; dd < 4; dd++) acc[i][dd] *= corr;
        }

        __syncthreads();
#pragma unroll
        for (int j = 0; j < 4; j++) {
            int key = (tx << 2) + j;
            int swp = key & 31;
            *(float4*)&Pts[key][((2 * ty) ^ swp) << 2] =
                make_float4(s_[0][j], s_[1][j], s_[2][j], s_[3][j]);
            *(float4*)&Pts[key][((2 * ty + 1) ^ swp) << 2] =
                make_float4(s_[4][j], s_[5][j], s_[6][j], s_[7][j]);
        }
        __syncthreads();

#pragma unroll 8
        for (int j = 0; j < 64; j++) {
            int swp = j & 31;
            float4 pp0 = *(const float4*)&Pts[j][((2 * ty) ^ swp) << 2];
            float4 pp1 = *(const float4*)&Pts[j][((2 * ty + 1) ^ swp) << 2];
            float4 v4 = *(const float4*)&Vs[j][tx << 2];
            float pf[8] = {pp0.x,pp0.y,pp0.z,pp0.w, pp1.x,pp1.y,pp1.z,pp1.w};
            float vf[4] = {v4.x, v4.y, v4.z, v4.w};
#pragma unroll
            for (int i = 0; i < 8; i++)
#pragma unroll
                for (int dd = 0; dd < 4; dd++)
                    acc[i][dd] += pf[i] * vf[dd];
        }
    }

#pragma unroll
    for (int i = 0; i < 8; i++) {
        float inv = 1.0f / l[i];
        int r = qt * 128 + (ty << 3) + i;
        *(float4*)(O + (rowbase + r) * EMB + h * HDIM + (tx << 2)) =
            make_float4(acc[i][0]*inv, acc[i][1]*inv, acc[i][2]*inv, acc[i][3]*inv);
    }
#endif
}

// ---------------------------------------------------------------------------
extern "C" void kernel_launch(void* const* d_in, const int* in_sizes, int n_in,
                              void* d_out, int out_size) {
    const float* query = (const float*)d_in[0];
    const float* key   = (const float*)d_in[1];
    const float* value = (const float*)d_in[2];
    const float* Wq    = (const float*)d_in[3];
    const float* Wk    = (const float*)d_in[4];
    const float* Wv    = (const float*)d_in[5];
    const float* Wo    = (const float*)d_in[6];
    float* out = (float*)d_out;

    __nv_bfloat16 *qh, *ql, *kh, *kl, *vth, *vtl;
    float *ctx;
    cudaGetSymbolAddress((void**)&qh,  g_qh);
    cudaGetSymbolAddress((void**)&ql,  g_ql);
    cudaGetSymbolAddress((void**)&kh,  g_kh);
    cudaGetSymbolAddress((void**)&kl,  g_kl);
    cudaGetSymbolAddress((void**)&vth, g_vth);
    cudaGetSymbolAddress((void**)&vtl, g_vtl);
    cudaGetSymbolAddress((void**)&ctx, g_ctx);

    cudaFuncSetAttribute(gemm_tc_kernel,
                         cudaFuncAttributeMaxDynamicSharedMemorySize, GSMEM);
    cudaFuncSetAttribute(attention_kernel,
                         cudaFuncAttributeMaxDynamicSharedMemorySize, ASMEM);

    const float qscale = 0.125f * 1.44269504088896340736f;
    dim3 gg(EMB / 128, MTOT / 128);
    gemm_tc_kernel<<<gg, 256, GSMEM>>>(query, Wq, nullptr, qh, ql, GM_SPLIT, qscale);
    gemm_tc_kernel<<<gg, 256, GSMEM>>>(key,   Wk, nullptr, kh, kl, GM_SPLIT, 1.0f);
    gemm_tc_kernel<<<gg, 256, GSMEM>>>(value, Wv, nullptr, vth, vtl, GM_SPLITT, 1.0f);
    attention_kernel<<<dim3(SEQ / AQ, NHEAD, BATCH), 256, ASMEM>>>(qh, ql, kh, kl, vth, vtl, ctx);
    gemm_tc_kernel<<<gg, 256, GSMEM>>>(ctx, Wo, out, nullptr, nullptr, GM_F32, 1.0f);
}